// round 14
// baseline (speedup 1.0000x reference)
#include <cuda_runtime.h>
#include <cstdint>

#define B_SZ   512
#define PX     512
#define PH     1024
#define PL     4
#define PVT    512
#define PET    256
#define NG     4096      // 4 gates * PH (interleaved col space: col = 4h+g)
#define HID    4096      // PL * PH
#define IN_DIM 2560
#define IN0    1536      // PX + PH
#define NHEAD  768       // PVT + PET

#define BM 64
#define BN 128
#define BK 16
#define RS 20            // smem row stride (floats), conflict-free for frag LDS
#define KS_TAIL 4        // tail split-K factor (K=256 each)
#define KS_HEAD 8        // heads split-K factor (K=512 each)

// Scratch (no allocations allowed)
__device__ float g_Gp[PL * B_SZ * NG];          // MODE0 partials (interleaved cols)
__device__ float g_Tp[KS_TAIL * B_SZ * NG];     // tail split-K slices
__device__ float g_Hs[KS_HEAD * B_SZ * NHEAD];  // head split-K slices
__device__ float g_hidden[B_SZ * HID];          // concat hidden (tf32-rounded)
__device__ float g_A0[PL * B_SZ * IN0];         // tf32-rounded [x | h_prev[l]]
__device__ unsigned g_cnt[(B_SZ / BM) * (NG / BN)];   // split-K arrival counters (256)

__device__ __forceinline__ uint32_t cvt_tf32(float x) {
    uint32_t r; asm("cvt.rna.tf32.f32 %0, %1;" : "=r"(r) : "f"(x)); return r;
}
__device__ __forceinline__ float cvtf(float x) { return __uint_as_float(cvt_tf32(x)); }
__device__ __forceinline__ void cp16(uint32_t dst, const void* src) {
    asm volatile("cp.async.cg.shared.global [%0], [%1], 16;" :: "r"(dst), "l"(src));
}
__device__ __forceinline__ void mma_tf32(float (&d)[4], const uint32_t (&a)[4],
                                         uint32_t b0, uint32_t b1) {
    asm volatile(
        "mma.sync.aligned.m16n8k8.row.col.f32.tf32.tf32.f32 "
        "{%0,%1,%2,%3}, {%4,%5,%6,%7}, {%8,%9}, {%0,%1,%2,%3};\n"
        : "+f"(d[0]), "+f"(d[1]), "+f"(d[2]), "+f"(d[3])
        : "r"(a[0]), "r"(a[1]), "r"(a[2]), "r"(a[3]), "r"(b0), "r"(b1));
}
__device__ __forceinline__ float sigm(float x) { return 1.f / (1.f + __expf(-x)); }

// launch-time: build tf32-rounded [x | h_prev[l]] concat per layer
__global__ void prep_A0(const float* __restrict__ x, const float* __restrict__ h_prev) {
    const int i = blockIdx.x * blockDim.x + threadIdx.x;   // float4 index
    const int c  = (i * 4) % IN0;
    const int lb = (i * 4) / IN0;          // l * B_SZ + b
    const float4 v = (c < PX)
        ? *(const float4*)&x[(size_t)(lb % B_SZ) * PX + c]
        : *(const float4*)&h_prev[(size_t)lb * PH + (c - PX)];
    ((float4*)g_A0)[i] = make_float4(cvtf(v.x), cvtf(v.y), cvtf(v.z), cvtf(v.w));
}

// MODE 0: gates, all layers (grid.z=layer), K=1536. lz==0 -> fused pointwise -> g_hidden,
//         lz>0 -> +interleaved bias -> g_Gp.
// MODE 1: grid.z in 0..KS_TAIL-1: tail slice for `layer` (K=256) -> g_Tp; the LAST
//         finishing CTA per (bm,bn) tile fuses the LSTM pointwise -> g_hidden.
//         grid.z in KS_TAIL..KS_TAIL+1: head slice kz = 2*(layer-1)+(z-KS_TAIL)
//         (K=512, reads hidden of layer-1, ready) -> g_Hs.
// MODE 2: head slices kz = 6,7 (grid.z + 6) -> g_Hs.
// Weights consumed RAW (fp32 bits -> implicit tf32 truncation in HMMA).
template<int MODE>
__global__ void __launch_bounds__(256, 3)
gemm_tf32(const float* __restrict__ c_prev,
          const float* __restrict__ bg,
          const float* __restrict__ Wg,
          const float* __restrict__ W_y,
          const float* __restrict__ W_E,
          int layer)
{
    extern __shared__ float smem[];

    const int tid = threadIdx.x;
    const int bm  = blockIdx.y * BM;
    const int bn  = blockIdx.x * BN;
    const int lz  = (MODE == 0) ? blockIdx.z : layer;

    bool is_head = (MODE == 2);
    int kz = 0;
    if (MODE == 1) {
        if (blockIdx.z >= KS_TAIL) {
            is_head = true;
            if (bn >= NHEAD) return;                       // head grid is 6 x-tiles
            kz = 2 * (layer - 1) + ((int)blockIdx.z - KS_TAIL);
        } else {
            kz = blockIdx.z;
        }
    } else if (MODE == 2) {
        kz = (int)blockIdx.z + 6;
    }

    const int Ktot = (MODE == 0) ? IN0
                   : (is_head ? (HID / KS_HEAD) : (PH / KS_TAIL));
    const int nT = Ktot / BK;                  // 96 / 32 / 16

    // A loader: 64x16 floats -> 1 float4/thread
    const int lrowA = tid >> 2;                // 0..63
    const int kqA   = (tid & 3) * 4;           // 0,4,8,12
    // B loader: 128x16 floats -> 2 float4/thread
    const int lrowB = tid >> 1;                // 0..127
    const int kqB   = (tid & 1) * 8;           // 0,8

    const uint32_t sBase = (uint32_t)__cvta_generic_to_shared(smem);
    const uint32_t ldA = (uint32_t)(lrowA * RS + kqA) * 4u;
    const uint32_t ldB = (uint32_t)(lrowB * RS + kqB) * 4u;

    const int warp = tid >> 5;
    const int lane = tid & 31;
    const int grp  = lane >> 2;
    const int q    = lane & 3;
    const int wm   = (warp & 1) * 32;
    const int wn   = (warp >> 1) * 32;

    float acc[2][4][4];
    #pragma unroll
    for (int i = 0; i < 2; i++)
        #pragma unroll
        for (int j = 0; j < 4; j++)
            #pragma unroll
            for (int v = 0; v < 4; v++) acc[i][j][v] = 0.f;

    // interleaved weight row for gate GEMMs: col gn -> row (gn&3)*PH + (gn>>2)
    const int gn    = bn + lrowB;
    const int wrowI = (gn & 3) * PH + (gn >> 2);

    // invariant source row pointers
    const float* pa_row;
    const float* pb_row;
    if (MODE == 0) {
        pa_row = g_A0 + ((size_t)lz * B_SZ + bm + lrowA) * IN0;
        pb_row = Wg + ((size_t)lz * NG + wrowI) * IN_DIM;
    } else if (!is_head) {
        pa_row = g_hidden + (size_t)(bm + lrowA) * HID + (layer - 1) * PH
               + kz * (PH / KS_TAIL);
        pb_row = Wg + ((size_t)layer * NG + wrowI) * IN_DIM + IN0
               + kz * (PH / KS_TAIL);
    } else {
        pa_row = g_hidden + (size_t)(bm + lrowA) * HID + kz * (HID / KS_HEAD);
        pb_row = (gn < PVT) ? W_y + (size_t)gn * HID + kz * (HID / KS_HEAD)
                            : W_E + (size_t)(gn - PVT) * HID + kz * (HID / KS_HEAD);
    }

    auto load_stage = [&](int buf, int s) {
        const int gkA = s * BK + kqA;
        const uint32_t da = sBase + (uint32_t)buf * ((BM + BN) * RS * 4) + ldA;
        cp16(da, pa_row + gkA);
        const int gkB = s * BK + kqB;
        const uint32_t db = sBase + (uint32_t)buf * ((BM + BN) * RS * 4)
                          + (uint32_t)(BM * RS * 4) + ldB;
        cp16(db, pb_row + gkB); cp16(db + 16, pb_row + gkB + 4);
    };

    load_stage(0, 0);
    asm volatile("cp.async.commit_group;");
    load_stage(1, 1);
    asm volatile("cp.async.commit_group;");

    for (int s = 0; s < nT; s++) {
        const int buf = s % 3;
        if (s + 1 < nT) { asm volatile("cp.async.wait_group 1;"); }
        else            { asm volatile("cp.async.wait_group 0;"); }
        __syncthreads();                       // stage s visible; MMA(s-1) done everywhere
        if (s + 2 < nT) {
            load_stage((s + 2) % 3, s + 2);    // overwrites stage s-1's buffer (safe)
            asm volatile("cp.async.commit_group;");
        }

        const float* __restrict__ Ab = smem + buf * ((BM + BN) * RS);
        const float* __restrict__ Bb = Ab + BM * RS;
        #pragma unroll
        for (int kk = 0; kk < BK; kk += 8) {
            uint32_t a[2][4];
            #pragma unroll
            for (int im = 0; im < 2; im++) {
                const int r = wm + im * 16 + grp;
                a[im][0] = __float_as_uint(Ab[(r    ) * RS + kk + q    ]);
                a[im][1] = __float_as_uint(Ab[(r + 8) * RS + kk + q    ]);
                a[im][2] = __float_as_uint(Ab[(r    ) * RS + kk + q + 4]);
                a[im][3] = __float_as_uint(Ab[(r + 8) * RS + kk + q + 4]);
            }
            #pragma unroll
            for (int jn = 0; jn < 4; jn++) {
                const int n = wn + jn * 8 + grp;
                const uint32_t b0 = __float_as_uint(Bb[n * RS + kk + q    ]);
                const uint32_t b1 = __float_as_uint(Bb[n * RS + kk + q + 4]);
                mma_tf32(acc[0][jn], a[0], b0, b1);
                mma_tf32(acc[1][jn], a[1], b0, b1);
            }
        }
    }

    // ================= epilogues =================
    if (MODE == 0 && lz == 0) {
        // fused LSTM pointwise for layer 0 (full K in this CTA)
        __syncthreads();
        float* st = smem;                      // 64 x 132 floats = 33792 B
        #pragma unroll
        for (int im = 0; im < 2; im++) {
            const int rl = wm + im * 16 + grp;
            #pragma unroll
            for (int jn = 0; jn < 4; jn++) {
                const int cl = wn + jn * 8 + 2 * q;
                *(float2*)&st[rl * 132 + cl]       = make_float2(acc[im][jn][0], acc[im][jn][1]);
                *(float2*)&st[(rl + 8) * 132 + cl] = make_float2(acc[im][jn][2], acc[im][jn][3]);
            }
        }
        __syncthreads();

        const int hc = tid & 31;
        const int h  = (bn >> 2) + hc;
        #pragma unroll 1
        for (int pass = 0; pass < 8; pass++) {
            const int row = pass * 8 + (tid >> 5);
            const int gb  = bm + row;
            float4 g = *(const float4*)&st[row * 132 + 4 * hc];
            g.x += bg[0 * PH + h];
            g.y += bg[1 * PH + h];
            g.z += bg[2 * PH + h];
            g.w += bg[3 * PH + h];
            const float ig = sigm(g.x);
            const float fg = sigm(g.y);
            const float og = sigm(g.z);
            const float sg = tanhf(g.w);
            const float cp = c_prev[(size_t)gb * PH + h];
            const float cn = fg * cp + ig * sg;
            g_hidden[(size_t)gb * HID + h] = cvtf(og * tanhf(cn));
        }
        return;
    }

    if (MODE == 0) {
        // lz > 0: partial + interleaved bias -> g_Gp
        #pragma unroll
        for (int jn = 0; jn < 4; jn++) {
            const int c0 = bn + wn + jn * 8 + 2 * q;
            const int h  = c0 >> 2;
            const int g0 = c0 & 3;
            const float b0 = bg[(size_t)lz * NG + g0 * PH + h];
            const float b1 = bg[(size_t)lz * NG + (g0 + 1) * PH + h];
            #pragma unroll
            for (int im = 0; im < 2; im++) {
                const int r0 = bm + wm + im * 16 + grp;
                *(float2*)&g_Gp[((size_t)lz * B_SZ + r0    ) * NG + c0]
                    = make_float2(acc[im][jn][0] + b0, acc[im][jn][1] + b1);
                *(float2*)&g_Gp[((size_t)lz * B_SZ + r0 + 8) * NG + c0]
                    = make_float2(acc[im][jn][2] + b0, acc[im][jn][3] + b1);
            }
        }
        return;
    }

    if (is_head) {
        float* sc = g_Hs + (size_t)kz * B_SZ * NHEAD;
        #pragma unroll
        for (int im = 0; im < 2; im++) {
            const int r0 = bm + wm + im * 16 + grp;
            #pragma unroll
            for (int jn = 0; jn < 4; jn++) {
                const int c0 = bn + wn + jn * 8 + 2 * q;
                *(float2*)&sc[(size_t)(r0    ) * NHEAD + c0]
                    = make_float2(acc[im][jn][0], acc[im][jn][1]);
                *(float2*)&sc[(size_t)(r0 + 8) * NHEAD + c0]
                    = make_float2(acc[im][jn][2], acc[im][jn][3]);
            }
        }
        return;
    }

    // ---- MODE 1 tail slice: store, then last-arriving CTA fuses pointwise ----
    {
        float* sc = g_Tp + (size_t)kz * B_SZ * NG;
        #pragma unroll
        for (int im = 0; im < 2; im++) {
            const int r0 = bm + wm + im * 16 + grp;
            #pragma unroll
            for (int jn = 0; jn < 4; jn++) {
                const int c0 = bn + wn + jn * 8 + 2 * q;
                *(float2*)&sc[(size_t)(r0    ) * NG + c0]
                    = make_float2(acc[im][jn][0], acc[im][jn][1]);
                *(float2*)&sc[(size_t)(r0 + 8) * NG + c0]
                    = make_float2(acc[im][jn][2], acc[im][jn][3]);
            }
        }

        __shared__ unsigned s_last;
        __threadfence();                        // publish this thread's slice stores
        __syncthreads();
        const int tile = blockIdx.y * (NG / BN) + blockIdx.x;
        if (tid == 0) {
            const unsigned old = atomicAdd(&g_cnt[tile], 1u);
            s_last = (old == KS_TAIL - 1) ? 1u : 0u;
        }
        __syncthreads();
        if (!s_last) return;
        __threadfence();                        // acquire other CTAs' slices

        // pointwise for tile (bm, bn): 64 rows x 32 hidden cols; fixed sum order
        #pragma unroll 1
        for (int e = 0; e < 8; e++) {
            const int t   = tid + e * 256;
            const int row = t >> 5;             // 0..63
            const int hc  = t & 31;
            const int gb  = bm + row;
            const int h   = (bn >> 2) + hc;
            const size_t off = (size_t)gb * NG + bn + 4 * hc;
            float4 g = *(const float4*)&g_Gp[(size_t)layer * B_SZ * NG + off];
            #pragma unroll
            for (int kzi = 0; kzi < KS_TAIL; kzi++) {
                const float4 tt = *(const float4*)&g_Tp[(size_t)kzi * B_SZ * NG + off];
                g.x += tt.x; g.y += tt.y; g.z += tt.z; g.w += tt.w;
            }
            const float ig = sigm(g.x);
            const float fg = sigm(g.y);
            const float og = sigm(g.z);
            const float sg = tanhf(g.w);
            const float cp = c_prev[((size_t)layer * B_SZ + gb) * PH + h];
            const float cn = fg * cp + ig * sg;
            g_hidden[(size_t)gb * HID + layer * PH + h] = cvtf(og * tanhf(cn));
        }
        if (tid == 0) g_cnt[tile] = 0;          // self-clean for graph replay
    }
}

// sum 8 head K-slices + bias -> split d_out layout
__global__ void reduce_heads(const float* __restrict__ b_y,
                             const float* __restrict__ b_E,
                             float* __restrict__ out)
{
    const int idx = (blockIdx.x * blockDim.x + threadIdx.x) * 4;
    const int r = idx / NHEAD;
    const int c = idx % NHEAD;
    float4 s = *(const float4*)&g_Hs[idx];
    #pragma unroll
    for (int kzi = 1; kzi < KS_HEAD; kzi++) {
        const float4 t = *(const float4*)&g_Hs[(size_t)kzi * B_SZ * NHEAD + idx];
        s.x += t.x; s.y += t.y; s.z += t.z; s.w += t.w;
    }
    if (c < PVT) {
        const float4 b = *(const float4*)&b_y[c];
        s.x += b.x; s.y += b.y; s.z += b.z; s.w += b.w;
        *(float4*)&out[(size_t)r * PVT + c] = s;
    } else {
        const int c2 = c - PVT;
        const float4 b = *(const float4*)&b_E[c2];
        s.x += b.x; s.y += b.y; s.z += b.z; s.w += b.w;
        *(float4*)&out[(size_t)B_SZ * PVT + (size_t)r * PET + c2] = s;
    }
}

extern "C" void kernel_launch(void* const* d_in, const int* in_sizes, int n_in,
                              void* d_out, int out_size) {
    const float* x      = (const float*)d_in[0];
    const float* h_prev = (const float*)d_in[1];
    const float* c_prev = (const float*)d_in[2];
    const float* Wg     = (const float*)d_in[3];
    const float* bg     = (const float*)d_in[4];
    const float* W_y    = (const float*)d_in[5];
    const float* b_y    = (const float*)d_in[6];
    const float* W_E    = (const float*)d_in[7];
    const float* b_E    = (const float*)d_in[8];
    float* out = (float*)d_out;

    const int SMB = 3 * (BM + BN) * RS * (int)sizeof(float);   // 46080 <= 48KB default
    const dim3 blk(256);

    // 0) tf32-rounded activation concat (weights consumed raw -> HW truncation)
    prep_A0<<<(PL * B_SZ * IN0 / 4 + 255) / 256, 256>>>(x, h_prev);

    // 1) gates for all 4 layers (K=1536); layer 0 fuses pointwise -> g_hidden
    gemm_tf32<0><<<dim3(NG / BN, B_SZ / BM, PL), blk, SMB>>>(
        c_prev, bg, Wg, W_y, W_E, 0);
    // 2) layers 1..3: tail split-K x4 (fused pointwise via arrival counter)
    //    + 2 head K-slices of the PREVIOUS layer's hidden piggybacked per launch
    for (int l = 1; l < PL; l++)
        gemm_tf32<1><<<dim3(NG / BN, B_SZ / BM, KS_TAIL + 2), blk, SMB>>>(
            c_prev, bg, Wg, W_y, W_E, l);
    // 3) remaining head slices 6,7 (layer 3 hidden)
    gemm_tf32<2><<<dim3(NHEAD / BN, B_SZ / BM, 2), blk, SMB>>>(
        c_prev, bg, Wg, W_y, W_E, 0);
    // 4) reduce head slices + bias -> d_out
    reduce_heads<<<(B_SZ * NHEAD / 4) / 256, 256>>>(b_y, b_E, out);
}

// round 15
// speedup vs baseline: 1.6868x; 1.6868x over previous
#include <cuda_runtime.h>
#include <cstdint>

#define B_SZ   512
#define PX     512
#define PH     1024
#define PL     4
#define PVT    512
#define PET    256
#define NG     4096      // 4 gates * PH (interleaved col space: col = 4h+g)
#define HID    4096      // PL * PH
#define IN_DIM 2560
#define IN0    1536      // PX + PH
#define NHEAD  768       // PVT + PET

#define BM 64
#define BN 128
#define BK 16
#define RS 20            // smem row stride (floats), conflict-free for frag LDS
#define KS_TAIL 4        // tail split-K factor (K=256 each)
#define KS_HEAD 8        // heads split-K factor (K=512 each)

// Scratch (no allocations allowed)
__device__ float g_Gp[PL * B_SZ * NG];          // MODE0 partials (interleaved cols)
__device__ float g_Tp[KS_TAIL * B_SZ * NG];     // tail split-K slices
__device__ float g_Hs[KS_HEAD * B_SZ * NHEAD];  // head split-K slices
__device__ float g_hidden[B_SZ * HID];          // concat hidden (tf32-rounded)
__device__ float g_A0[PL * B_SZ * IN0];         // tf32-rounded [x | h_prev[l]]

__device__ __forceinline__ uint32_t cvt_tf32(float x) {
    uint32_t r; asm("cvt.rna.tf32.f32 %0, %1;" : "=r"(r) : "f"(x)); return r;
}
__device__ __forceinline__ float cvtf(float x) { return __uint_as_float(cvt_tf32(x)); }
__device__ __forceinline__ void cp16(uint32_t dst, const void* src) {
    asm volatile("cp.async.cg.shared.global [%0], [%1], 16;" :: "r"(dst), "l"(src));
}
__device__ __forceinline__ void mma_tf32(float (&d)[4], const uint32_t (&a)[4],
                                         uint32_t b0, uint32_t b1) {
    asm volatile(
        "mma.sync.aligned.m16n8k8.row.col.f32.tf32.tf32.f32 "
        "{%0,%1,%2,%3}, {%4,%5,%6,%7}, {%8,%9}, {%0,%1,%2,%3};\n"
        : "+f"(d[0]), "+f"(d[1]), "+f"(d[2]), "+f"(d[3])
        : "r"(a[0]), "r"(a[1]), "r"(a[2]), "r"(a[3]), "r"(b0), "r"(b1));
}
__device__ __forceinline__ float sigm(float x) { return 1.f / (1.f + __expf(-x)); }

// launch-time: build tf32-rounded [x | h_prev[l]] concat per layer
__global__ void prep_A0(const float* __restrict__ x, const float* __restrict__ h_prev) {
    const int i = blockIdx.x * blockDim.x + threadIdx.x;   // float4 index
    const int c  = (i * 4) % IN0;
    const int lb = (i * 4) / IN0;          // l * B_SZ + b
    const float4 v = (c < PX)
        ? *(const float4*)&x[(size_t)(lb % B_SZ) * PX + c]
        : *(const float4*)&h_prev[(size_t)lb * PH + (c - PX)];
    ((float4*)g_A0)[i] = make_float4(cvtf(v.x), cvtf(v.y), cvtf(v.z), cvtf(v.w));
}

// MODE 0: gates, all layers (grid.z=layer), K=1536. lz==0 -> fused pointwise -> g_hidden,
//         lz>0 -> +interleaved bias -> g_Gp.
// MODE 1: tail slice for `layer` (grid.z=kz in 0..3), K=256 -> g_Tp slice.
// MODE 2: head slices kz = layer + blockIdx.z (layer = kz_base in {0,2,4,6}),
//         K=512 each, reads hidden cols [kz*512,(kz+1)*512) -> g_Hs slice.
// Weights consumed RAW (fp32 bits -> implicit tf32 truncation in HMMA).
template<int MODE>
__global__ void __launch_bounds__(256, 3)
gemm_tf32(const float* __restrict__ c_prev,
          const float* __restrict__ bg,
          const float* __restrict__ Wg,
          const float* __restrict__ W_y,
          const float* __restrict__ W_E,
          int layer)
{
    extern __shared__ float smem[];

    const int tid = threadIdx.x;
    const int bm  = blockIdx.y * BM;
    const int bn  = blockIdx.x * BN;
    const int lz  = (MODE == 0) ? blockIdx.z : layer;
    const int kz  = (MODE == 0) ? 0
                  : ((MODE == 1) ? (int)blockIdx.z : layer + (int)blockIdx.z);

    const int Ktot = (MODE == 0) ? IN0 : ((MODE == 1) ? PH / KS_TAIL : HID / KS_HEAD);
    const int nT = Ktot / BK;                 // 96 / 16 / 32

    // A loader: 64x16 floats -> 1 float4/thread
    const int lrowA = tid >> 2;               // 0..63
    const int kqA   = (tid & 3) * 4;          // 0,4,8,12
    // B loader: 128x16 floats -> 2 float4/thread
    const int lrowB = tid >> 1;               // 0..127
    const int kqB   = (tid & 1) * 8;          // 0,8

    const uint32_t sBase = (uint32_t)__cvta_generic_to_shared(smem);
    const uint32_t ldA = (uint32_t)(lrowA * RS + kqA) * 4u;
    const uint32_t ldB = (uint32_t)(lrowB * RS + kqB) * 4u;

    const int warp = tid >> 5;
    const int lane = tid & 31;
    const int grp  = lane >> 2;
    const int q    = lane & 3;
    const int wm   = (warp & 1) * 32;
    const int wn   = (warp >> 1) * 32;

    float acc[2][4][4];
    #pragma unroll
    for (int i = 0; i < 2; i++)
        #pragma unroll
        for (int j = 0; j < 4; j++)
            #pragma unroll
            for (int v = 0; v < 4; v++) acc[i][j][v] = 0.f;

    // interleaved weight row for gate GEMMs: col gn -> row (gn&3)*PH + (gn>>2)
    const int gn    = bn + lrowB;
    const int wrowI = (gn & 3) * PH + (gn >> 2);

    // invariant source row pointers
    const float* pa_row;
    const float* pb_row;
    if (MODE == 0) {
        pa_row = g_A0 + ((size_t)lz * B_SZ + bm + lrowA) * IN0;
        pb_row = Wg + ((size_t)lz * NG + wrowI) * IN_DIM;
    } else if (MODE == 1) {
        pa_row = g_hidden + (size_t)(bm + lrowA) * HID + (layer - 1) * PH
               + kz * (PH / KS_TAIL);
        pb_row = Wg + ((size_t)layer * NG + wrowI) * IN_DIM + IN0
               + kz * (PH / KS_TAIL);
    } else {
        pa_row = g_hidden + (size_t)(bm + lrowA) * HID + kz * (HID / KS_HEAD);
        pb_row = (gn < PVT) ? W_y + (size_t)gn * HID + kz * (HID / KS_HEAD)
                            : W_E + (size_t)(gn - PVT) * HID + kz * (HID / KS_HEAD);
    }

    auto load_stage = [&](int buf, int s) {
        const int gkA = s * BK + kqA;
        const uint32_t da = sBase + (uint32_t)buf * ((BM + BN) * RS * 4) + ldA;
        cp16(da, pa_row + gkA);
        const int gkB = s * BK + kqB;
        const uint32_t db = sBase + (uint32_t)buf * ((BM + BN) * RS * 4)
                          + (uint32_t)(BM * RS * 4) + ldB;
        cp16(db, pb_row + gkB); cp16(db + 16, pb_row + gkB + 4);
    };

    load_stage(0, 0);
    asm volatile("cp.async.commit_group;");
    load_stage(1, 1);
    asm volatile("cp.async.commit_group;");

    for (int s = 0; s < nT; s++) {
        const int buf = s % 3;
        if (s + 1 < nT) { asm volatile("cp.async.wait_group 1;"); }
        else            { asm volatile("cp.async.wait_group 0;"); }
        __syncthreads();                       // stage s visible; MMA(s-1) done everywhere
        if (s + 2 < nT) {
            load_stage((s + 2) % 3, s + 2);    // overwrites stage s-1's buffer (safe)
            asm volatile("cp.async.commit_group;");
        }

        const float* __restrict__ Ab = smem + buf * ((BM + BN) * RS);
        const float* __restrict__ Bb = Ab + BM * RS;
        #pragma unroll
        for (int kk = 0; kk < BK; kk += 8) {
            uint32_t a[2][4];
            #pragma unroll
            for (int im = 0; im < 2; im++) {
                const int r = wm + im * 16 + grp;
                a[im][0] = __float_as_uint(Ab[(r    ) * RS + kk + q    ]);
                a[im][1] = __float_as_uint(Ab[(r + 8) * RS + kk + q    ]);
                a[im][2] = __float_as_uint(Ab[(r    ) * RS + kk + q + 4]);
                a[im][3] = __float_as_uint(Ab[(r + 8) * RS + kk + q + 4]);
            }
            #pragma unroll
            for (int jn = 0; jn < 4; jn++) {
                const int n = wn + jn * 8 + grp;
                const uint32_t b0 = __float_as_uint(Bb[n * RS + kk + q    ]);
                const uint32_t b1 = __float_as_uint(Bb[n * RS + kk + q + 4]);
                mma_tf32(acc[0][jn], a[0], b0, b1);
                mma_tf32(acc[1][jn], a[1], b0, b1);
            }
        }
    }

    // ================= epilogues =================
    if (MODE == 0 && lz == 0) {
        // fused LSTM pointwise for layer 0 (full K in this CTA)
        __syncthreads();                       // all warps done with smem tiles
        float* st = smem;                      // 64 x 132 floats = 33792 B
        #pragma unroll
        for (int im = 0; im < 2; im++) {
            const int rl = wm + im * 16 + grp;
            #pragma unroll
            for (int jn = 0; jn < 4; jn++) {
                const int cl = wn + jn * 8 + 2 * q;
                *(float2*)&st[rl * 132 + cl]       = make_float2(acc[im][jn][0], acc[im][jn][1]);
                *(float2*)&st[(rl + 8) * 132 + cl] = make_float2(acc[im][jn][2], acc[im][jn][3]);
            }
        }
        __syncthreads();

        const int hc = tid & 31;
        const int h  = (bn >> 2) + hc;
        #pragma unroll 1
        for (int pass = 0; pass < 8; pass++) {
            const int row = pass * 8 + (tid >> 5);
            const int gb  = bm + row;
            float4 g = *(const float4*)&st[row * 132 + 4 * hc];
            g.x += bg[0 * PH + h];
            g.y += bg[1 * PH + h];
            g.z += bg[2 * PH + h];
            g.w += bg[3 * PH + h];
            const float ig = sigm(g.x);
            const float fg = sigm(g.y);
            const float og = sigm(g.z);
            const float sg = tanhf(g.w);
            const float cp = c_prev[(size_t)gb * PH + h];
            const float cn = fg * cp + ig * sg;
            g_hidden[(size_t)gb * HID + h] = cvtf(og * tanhf(cn));
        }
        return;
    }

    if (MODE == 0) {
        // lz > 0: partial + interleaved bias -> g_Gp
        #pragma unroll
        for (int jn = 0; jn < 4; jn++) {
            const int c0 = bn + wn + jn * 8 + 2 * q;
            const int h  = c0 >> 2;
            const int g0 = c0 & 3;
            const float b0 = bg[(size_t)lz * NG + g0 * PH + h];
            const float b1 = bg[(size_t)lz * NG + (g0 + 1) * PH + h];
            #pragma unroll
            for (int im = 0; im < 2; im++) {
                const int r0 = bm + wm + im * 16 + grp;
                *(float2*)&g_Gp[((size_t)lz * B_SZ + r0    ) * NG + c0]
                    = make_float2(acc[im][jn][0] + b0, acc[im][jn][1] + b1);
                *(float2*)&g_Gp[((size_t)lz * B_SZ + r0 + 8) * NG + c0]
                    = make_float2(acc[im][jn][2] + b0, acc[im][jn][3] + b1);
            }
        }
    } else if (MODE == 1) {
        float* sc = g_Tp + (size_t)kz * B_SZ * NG;
        #pragma unroll
        for (int im = 0; im < 2; im++) {
            const int r0 = bm + wm + im * 16 + grp;
            #pragma unroll
            for (int jn = 0; jn < 4; jn++) {
                const int c0 = bn + wn + jn * 8 + 2 * q;
                *(float2*)&sc[(size_t)(r0    ) * NG + c0]
                    = make_float2(acc[im][jn][0], acc[im][jn][1]);
                *(float2*)&sc[(size_t)(r0 + 8) * NG + c0]
                    = make_float2(acc[im][jn][2], acc[im][jn][3]);
            }
        }
    } else {
        float* sc = g_Hs + (size_t)kz * B_SZ * NHEAD;
        #pragma unroll
        for (int im = 0; im < 2; im++) {
            const int r0 = bm + wm + im * 16 + grp;
            #pragma unroll
            for (int jn = 0; jn < 4; jn++) {
                const int c0 = bn + wn + jn * 8 + 2 * q;
                *(float2*)&sc[(size_t)(r0    ) * NHEAD + c0]
                    = make_float2(acc[im][jn][0], acc[im][jn][1]);
                *(float2*)&sc[(size_t)(r0 + 8) * NHEAD + c0]
                    = make_float2(acc[im][jn][2], acc[im][jn][3]);
            }
        }
    }
}

// LSTM pointwise for layers 1..3: g = g_Gp[layer] (partial+bias) + 4 tail slices
__global__ void lstm_tail_pointwise(const float* __restrict__ c_prev, int layer) {
    const int idx = blockIdx.x * blockDim.x + threadIdx.x;   // one (b, h) each
    const int b = idx >> 10;
    const int h = idx & (PH - 1);
    const size_t off = (size_t)b * NG + 4 * h;
    float4 g = *(const float4*)&g_Gp[(size_t)layer * B_SZ * NG + off];
    #pragma unroll
    for (int kzi = 0; kzi < KS_TAIL; kzi++) {
        const float4 t = *(const float4*)&g_Tp[(size_t)kzi * B_SZ * NG + off];
        g.x += t.x; g.y += t.y; g.z += t.z; g.w += t.w;
    }
    const float ig = sigm(g.x);
    const float fg = sigm(g.y);
    const float og = sigm(g.z);
    const float sg = tanhf(g.w);
    const float cp = c_prev[((size_t)layer * B_SZ + b) * PH + h];
    const float cn = fg * cp + ig * sg;
    g_hidden[(size_t)b * HID + layer * PH + h] = cvtf(og * tanhf(cn));
}

// sum 8 head K-slices + bias -> split d_out layout
__global__ void reduce_heads(const float* __restrict__ b_y,
                             const float* __restrict__ b_E,
                             float* __restrict__ out)
{
    const int idx = (blockIdx.x * blockDim.x + threadIdx.x) * 4;
    const int r = idx / NHEAD;
    const int c = idx % NHEAD;
    float4 s = *(const float4*)&g_Hs[idx];
    #pragma unroll
    for (int kzi = 1; kzi < KS_HEAD; kzi++) {
        const float4 t = *(const float4*)&g_Hs[(size_t)kzi * B_SZ * NHEAD + idx];
        s.x += t.x; s.y += t.y; s.z += t.z; s.w += t.w;
    }
    if (c < PVT) {
        const float4 b = *(const float4*)&b_y[c];
        s.x += b.x; s.y += b.y; s.z += b.z; s.w += b.w;
        *(float4*)&out[(size_t)r * PVT + c] = s;
    } else {
        const int c2 = c - PVT;
        const float4 b = *(const float4*)&b_E[c2];
        s.x += b.x; s.y += b.y; s.z += b.z; s.w += b.w;
        *(float4*)&out[(size_t)B_SZ * PVT + (size_t)r * PET + c2] = s;
    }
}

extern "C" void kernel_launch(void* const* d_in, const int* in_sizes, int n_in,
                              void* d_out, int out_size) {
    const float* x      = (const float*)d_in[0];
    const float* h_prev = (const float*)d_in[1];
    const float* c_prev = (const float*)d_in[2];
    const float* Wg     = (const float*)d_in[3];
    const float* bg     = (const float*)d_in[4];
    const float* W_y    = (const float*)d_in[5];
    const float* b_y    = (const float*)d_in[6];
    const float* W_E    = (const float*)d_in[7];
    const float* b_E    = (const float*)d_in[8];
    float* out = (float*)d_out;

    // one-time stream/event setup (first call is the non-captured correctness run)
    static cudaStream_t s2 = nullptr;
    static cudaEvent_t ev[5];
    if (!s2) {
        cudaStreamCreateWithFlags(&s2, cudaStreamNonBlocking);
        for (int i = 0; i < 5; i++)
            cudaEventCreateWithFlags(&ev[i], cudaEventDisableTiming);
    }

    const int SMB = 3 * (BM + BN) * RS * (int)sizeof(float);   // 46080 <= 48KB default
    const dim3 blk(256);

    // 0) tf32-rounded activation concat (weights consumed raw -> HW truncation)
    prep_A0<<<(PL * B_SZ * IN0 / 4 + 255) / 256, 256>>>(x, h_prev);

    // 1) gates for all 4 layers (K=1536); layer 0 fuses pointwise -> g_hidden
    gemm_tf32<0><<<dim3(NG / BN, B_SZ / BM, PL), blk, SMB>>>(
        c_prev, bg, Wg, W_y, W_E, 0);
    // heads kz 0,1 (layer-0 hidden) concurrently on s2
    cudaEventRecord(ev[0], 0);
    cudaStreamWaitEvent(s2, ev[0], 0);
    gemm_tf32<2><<<dim3(NHEAD / BN, B_SZ / BM, 2), blk, SMB, s2>>>(
        c_prev, bg, Wg, W_y, W_E, 0);

    // 2) layers 1..3: tail split-K x4 (K=256 each) -> slices, then fused pointwise;
    //    head slices {2l, 2l+1} chase each layer's hidden on s2
    for (int l = 1; l < PL; l++) {
        gemm_tf32<1><<<dim3(NG / BN, B_SZ / BM, KS_TAIL), blk, SMB>>>(
            c_prev, bg, Wg, W_y, W_E, l);
        lstm_tail_pointwise<<<(B_SZ * PH) / 256, 256>>>(c_prev, l);
        cudaEventRecord(ev[l], 0);
        cudaStreamWaitEvent(s2, ev[l], 0);
        gemm_tf32<2><<<dim3(NHEAD / BN, B_SZ / BM, 2), blk, SMB, s2>>>(
            c_prev, bg, Wg, W_y, W_E, 2 * l);
    }

    // 3) join s2, then reduce head slices + bias -> d_out
    cudaEventRecord(ev[4], s2);
    cudaStreamWaitEvent(0, ev[4], 0);
    reduce_heads<<<(B_SZ * NHEAD / 4) / 256, 256>>>(b_y, b_E, out);
}